// round 7
// baseline (speedup 1.0000x reference)
#include <cuda_runtime.h>
#include <cstdint>

#define B_DIM 16
#define C_DIM 256
#define N_DIM 16384
#define K_DIM 8
#define NB 64
#define NST (N_DIM / NB)        // 256 super-tiles per b
#define GR 18                   // blocks per b
#define NSTAGES 10
#define KAPPA 20.0f

// ---- smem (floats) ----
// xA/xB: [256 c][36] stride-36 (16B-aligned rows; p1 cols & p2 float4 rows conflict-free)
#define XS 36
#define XBUF (C_DIM * XS)                 // 9216
#define XA_OFF 0
#define XB_OFF XBUF                       // 9216
#define PART_OFF (2 * XBUF)               // 18432 ; [16 w][512] xor-swizzled
#define PART_SIZE (16 * 512)              // 8192
#define Z_OFF (PART_OFF + PART_SIZE)      // 26624 ; z[n*8 + 4*(n>>4) + k]
#define Z_SIZE 528
#define S_OFF (Z_OFF + Z_SIZE)            // 27152
#define SM_FLOATS (S_OFF + 8)             // 27160
#define SMEM_BYTES (SM_FLOATS * 4)        // 108640 B -> 2 blocks/SM

__device__ float g_mu[B_DIM * C_DIM * K_DIM];
__device__ float g_M [B_DIM * C_DIM * K_DIM];
__device__ float g_S [B_DIM * K_DIM];

__device__ __forceinline__ float2 ffma2(float2 a, float2 b, float2 c) {
    float2 d;
    asm("fma.rn.f32x2 %0, %1, %2, %3;"
        : "=l"(reinterpret_cast<unsigned long long&>(d))
        : "l"(reinterpret_cast<unsigned long long&>(a)),
          "l"(reinterpret_cast<unsigned long long&>(b)),
          "l"(reinterpret_cast<unsigned long long&>(c)));
    return d;
}

__device__ __forceinline__ void cp_async16(uint32_t dst, const float* src) {
    asm volatile("cp.async.ca.shared.global [%0], [%1], 16;" :: "r"(dst), "l"(src));
}

__global__ void init_kernel(const float* __restrict__ mu_in) {
    int idx = blockIdx.x * blockDim.x + threadIdx.x;
    if (idx < B_DIM * C_DIM * K_DIM) {
        g_mu[idx] = mu_in[idx & (C_DIM * K_DIM - 1)];
        g_M[idx]  = 0.0f;
    }
    if (idx < B_DIM * K_DIM) g_S[idx] = 0.0f;
}

__global__ __launch_bounds__(512, 2)
void em_stage(const float* __restrict__ x, int last, float* __restrict__ z_out) {
    extern __shared__ float sm[];
    float* s_xA   = sm + XA_OFF;
    float* s_xB   = sm + XB_OFF;
    float* s_part = sm + PART_OFF;
    float* s_z    = sm + Z_OFF;
    float* s_S    = sm + S_OFF;

    uint32_t smb;
    asm("{ .reg .u64 t; cvta.to.shared.u64 t, %1; cvt.u32.u64 %0, t; }"
        : "=r"(smb) : "l"(sm));

    const int tid  = threadIdx.x;
    const int warp = tid >> 5, lane = tid & 31;
    const int b    = blockIdx.y;
    const float* xb = x + (size_t)b * C_DIM * N_DIM;

    // fill mapping: thread fills row (tid&255) of its group's buffer
    const int frow = tid & 255;
    const int grpB = tid >> 8;                       // 0: xA, 1: xB
    const uint32_t fdst = smb + ((grpB ? XB_OFF : XA_OFF) + frow * XS) * 4;
    const float* fsrc_row = xb + (size_t)frow * N_DIM + grpB * 32;

    // reduce mapping: one thread per (n,k)
    const int rn = tid >> 3, rk = tid & 7;

    // p2 mapping
    const int o   = warp >> 2;                       // n-quarter 0..3
    const int cp  = ((warp & 3) << 5) | lane;        // 0..127
    const float* p2x = (o < 2 ? s_xA : s_xB);
    const int nl  = (o & 1) << 4;                    // local n base in buffer
    const int ng  = o << 4;                          // global n base in super-tile

    if (tid < 8) s_S[tid] = 0.0f;

    float2 Ml[4] = {{0.f,0.f},{0.f,0.f},{0.f,0.f},{0.f,0.f}};
    float2 Mh[4] = {{0.f,0.f},{0.f,0.f},{0.f,0.f},{0.f,0.f}};
    float Sacc = 0.0f;

    const int t0 = blockIdx.x;

    // prologue: issue fills for super-tile t0
    {
        const float* src = fsrc_row + (size_t)t0 * NB;
        #pragma unroll
        for (int r = 0; r < 8; ++r)
            cp_async16(fdst + r * 16, src + r * 4);
        asm volatile("cp.async.commit_group;" ::: "memory");
    }

    const float* mub = g_mu + b * (C_DIM * K_DIM) + (warp << 4) * 8;

    for (int st = t0; st < NST; st += GR) {
        asm volatile("cp.async.wait_group 0;" ::: "memory");
        __syncthreads();

        // ===== phase 1: c-slice 16 per warp, lane covers n=lane & n=lane+32 =====
        {
            float2 A[8] = {{0.f,0.f},{0.f,0.f},{0.f,0.f},{0.f,0.f},
                           {0.f,0.f},{0.f,0.f},{0.f,0.f},{0.f,0.f}};
            const int cb = warp << 4;
            #pragma unroll
            for (int i = 0; i < 16; ++i) {
                float xa = s_xA[(cb + i) * XS + lane];
                float xv = s_xB[(cb + i) * XS + lane];
                float4 m0 = __ldg((const float4*)(mub + i * 8));
                float4 m1 = __ldg((const float4*)(mub + i * 8 + 4));
                float2 x0 = make_float2(xa, xa);
                float2 x1 = make_float2(xv, xv);
                A[0] = ffma2(x0, make_float2(m0.x, m0.y), A[0]);
                A[1] = ffma2(x0, make_float2(m0.z, m0.w), A[1]);
                A[2] = ffma2(x0, make_float2(m1.x, m1.y), A[2]);
                A[3] = ffma2(x0, make_float2(m1.z, m1.w), A[3]);
                A[4] = ffma2(x1, make_float2(m0.x, m0.y), A[4]);
                A[5] = ffma2(x1, make_float2(m0.z, m0.w), A[5]);
                A[6] = ffma2(x1, make_float2(m1.x, m1.y), A[6]);
                A[7] = ffma2(x1, make_float2(m1.z, m1.w), A[7]);
            }
            int sw = (lane >> 2) & 7;
            float* pb = s_part + (warp << 9) + (lane << 3);
            pb[0^sw]=A[0].x; pb[1^sw]=A[0].y; pb[2^sw]=A[1].x; pb[3^sw]=A[1].y;
            pb[4^sw]=A[2].x; pb[5^sw]=A[2].y; pb[6^sw]=A[3].x; pb[7^sw]=A[3].y;
            float* pb2 = pb + 256;                 // (lane+32)*8, same swizzle
            pb2[0^sw]=A[4].x; pb2[1^sw]=A[4].y; pb2[2^sw]=A[5].x; pb2[3^sw]=A[5].y;
            pb2[4^sw]=A[6].x; pb2[5^sw]=A[6].y; pb2[6^sw]=A[7].x; pb2[7^sw]=A[7].y;
        }
        __syncthreads();

        // ===== reduce over 16 slices + softmax: 1 thread per (n,k) =====
        {
            int col = (rn << 3) + (rk ^ ((rn >> 2) & 7));
            float v = 0.f;
            #pragma unroll
            for (int w = 0; w < 16; ++w)
                v += s_part[(w << 9) + col];
            v *= KAPPA;
            float mx = v;
            mx = fmaxf(mx, __shfl_xor_sync(~0u, mx, 1));
            mx = fmaxf(mx, __shfl_xor_sync(~0u, mx, 2));
            mx = fmaxf(mx, __shfl_xor_sync(~0u, mx, 4));
            float e = __expf(v - mx);
            float s = e;
            s += __shfl_xor_sync(~0u, s, 1);
            s += __shfl_xor_sync(~0u, s, 2);
            s += __shfl_xor_sync(~0u, s, 4);
            float z = e / s;
            s_z[(rn << 3) + ((rn >> 4) << 2) + rk] = z;
            Sacc += z;
            if (last)
                z_out[(((size_t)b * N_DIM + (size_t)st * NB + rn) << 3) + rk] = z;
        }
        __syncthreads();

        // ===== phase 2: c-pair {cp, cp+128} x 16 n, z broadcast =====
        {
            const float* xr0 = p2x + cp * XS + nl;
            const float* xr1 = p2x + (cp + 128) * XS + nl;
            #pragma unroll
            for (int q = 0; q < 4; ++q) {
                float4 xl4 = *(const float4*)(xr0 + 4 * q);
                float4 xh4 = *(const float4*)(xr1 + 4 * q);
                const float* xlv = (const float*)&xl4;
                const float* xhv = (const float*)&xh4;
                #pragma unroll
                for (int jj = 0; jj < 4; ++jj) {
                    int n = ng + 4 * q + jj;
                    const float* zr = s_z + (n << 3) + ((n >> 4) << 2);
                    float4 za = *(const float4*)(zr);
                    float4 zb = *(const float4*)(zr + 4);
                    float2 xl = make_float2(xlv[jj], xlv[jj]);
                    float2 xh = make_float2(xhv[jj], xhv[jj]);
                    Ml[0] = ffma2(xl, make_float2(za.x, za.y), Ml[0]);
                    Ml[1] = ffma2(xl, make_float2(za.z, za.w), Ml[1]);
                    Ml[2] = ffma2(xl, make_float2(zb.x, zb.y), Ml[2]);
                    Ml[3] = ffma2(xl, make_float2(zb.z, zb.w), Ml[3]);
                    Mh[0] = ffma2(xh, make_float2(za.x, za.y), Mh[0]);
                    Mh[1] = ffma2(xh, make_float2(za.z, za.w), Mh[1]);
                    Mh[2] = ffma2(xh, make_float2(zb.x, zb.y), Mh[2]);
                    Mh[3] = ffma2(xh, make_float2(zb.z, zb.w), Mh[3]);
                }
            }
        }
        // group barrier: my group's buffer fully consumed -> refill it
        if (grpB == 0) asm volatile("bar.sync 1, 256;" ::: "memory");
        else           asm volatile("bar.sync 2, 256;" ::: "memory");
        if (st + GR < NST) {
            const float* src = fsrc_row + (size_t)(st + GR) * NB;
            #pragma unroll
            for (int r = 0; r < 8; ++r)
                cp_async16(fdst + r * 16, src + r * 4);
            asm volatile("cp.async.commit_group;" ::: "memory");
        }
    }

    // ---- epilogue ----
    {
        float* Mp = g_M + ((size_t)b * C_DIM + cp) * K_DIM;
        float* Mq = g_M + ((size_t)b * C_DIM + cp + 128) * K_DIM;
        atomicAdd(Mp + 0, Ml[0].x); atomicAdd(Mp + 1, Ml[0].y);
        atomicAdd(Mp + 2, Ml[1].x); atomicAdd(Mp + 3, Ml[1].y);
        atomicAdd(Mp + 4, Ml[2].x); atomicAdd(Mp + 5, Ml[2].y);
        atomicAdd(Mp + 6, Ml[3].x); atomicAdd(Mp + 7, Ml[3].y);
        atomicAdd(Mq + 0, Mh[0].x); atomicAdd(Mq + 1, Mh[0].y);
        atomicAdd(Mq + 2, Mh[1].x); atomicAdd(Mq + 3, Mh[1].y);
        atomicAdd(Mq + 4, Mh[2].x); atomicAdd(Mq + 5, Mh[2].y);
        atomicAdd(Mq + 6, Mh[3].x); atomicAdd(Mq + 7, Mh[3].y);
    }
    // S: lane k = lane&7 across lanes with same k
    Sacc += __shfl_xor_sync(~0u, Sacc, 8);
    Sacc += __shfl_xor_sync(~0u, Sacc, 16);
    if (lane < 8) atomicAdd(s_S + lane, Sacc);
    __syncthreads();
    if (tid < 8) atomicAdd(g_S + b * K_DIM + tid, s_S[tid]);
}

__global__ void finalize_kernel(int last, float* __restrict__ mu_out) {
    const int k = blockIdx.x;
    const int b = blockIdx.y;
    const int c = threadIdx.x;
    __shared__ float red[256];

    float S = g_S[b * K_DIM + k];
    float val = g_M[((size_t)b * C_DIM + c) * K_DIM + k] / (1e-6f + S);

    red[c] = val * val;
    __syncthreads();
    for (int s = 128; s > 0; s >>= 1) {
        if (c < s) red[c] += red[c + s];
        __syncthreads();
    }
    float m = val / (1e-6f + sqrtf(red[0]));

    g_mu[((size_t)b * C_DIM + c) * K_DIM + k] = m;
    g_M [((size_t)b * C_DIM + c) * K_DIM + k] = 0.0f;
    if (c == 0) g_S[b * K_DIM + k] = 0.0f;
    if (last) mu_out[((size_t)b * K_DIM + k) * C_DIM + c] = m;
}

__global__ void zdiv_kernel(float* __restrict__ z) {
    int idx = blockIdx.x * blockDim.x + threadIdx.x;
    if (idx < B_DIM * N_DIM * K_DIM) {
        int k = idx & 7;
        int b = idx >> 17;
        z[idx] = z[idx] / (1e-6f + g_S[b * K_DIM + k]);
    }
}

extern "C" void kernel_launch(void* const* d_in, const int* in_sizes, int n_in,
                              void* d_out, int out_size) {
    const float* x     = (const float*)d_in[0];
    const float* mu_in = (const float*)d_in[1];
    float* out    = (float*)d_out;
    float* mu_out = out;
    float* z_out  = out + B_DIM * K_DIM * C_DIM;

    cudaFuncSetAttribute(em_stage, cudaFuncAttributeMaxDynamicSharedMemorySize, SMEM_BYTES);

    init_kernel<<<128, 256>>>(mu_in);
    for (int s = 0; s < NSTAGES; ++s) {
        int last = (s == NSTAGES - 1);
        em_stage<<<dim3(GR, B_DIM), 512, SMEM_BYTES>>>(x, last, z_out);
        if (last) zdiv_kernel<<<(B_DIM * N_DIM * K_DIM) / 256, 256>>>(z_out);
        finalize_kernel<<<dim3(K_DIM, B_DIM), 256>>>(last, mu_out);
    }
}

// round 8
// speedup vs baseline: 1.3951x; 1.3951x over previous
#include <cuda_runtime.h>

#define B_DIM 16
#define C_DIM 256
#define N_DIM 16384
#define K_DIM 8
#define NB 32
#define NT 512                  // 32n tiles per b
#define GR 32                   // blocks per b; block handles 16 tiles (8 pairs)
#define NSTAGES 10
#define KAPPA 20.0f

// ---- smem (floats) ----
#define SX_STRIDE 33
#define SX_SIZE (C_DIM * SX_STRIDE)        // 8448 per slot
#define MU_OFF  (2 * SX_SIZE)              // 16896
#define MU_SIZE (C_DIM * K_DIM)            // 2048
#define PART_OFF (MU_OFF + MU_SIZE)        // 18944 ; [16 warps][520] (64 vn x 8 k + pad)
#define PART_SIZE (16 * 520)               // 8320
#define Z_OFF (PART_OFF + PART_SIZE)       // 27264 ; z[vn*8 + 4*(vn>>4) + k]
#define Z_SIZE 528
#define S_OFF (Z_OFF + Z_SIZE)             // 27792
#define SM_FLOATS (S_OFF + 8)              // 27800
#define SMEM_BYTES (SM_FLOATS * 4)         // 111200 B -> 2 blocks/SM

__device__ float g_mu[B_DIM * C_DIM * K_DIM];
__device__ float g_M [B_DIM * C_DIM * K_DIM];
__device__ float g_S [B_DIM * K_DIM];

__device__ __forceinline__ float2 ffma2(float2 a, float2 b, float2 c) {
    float2 d;
    asm("fma.rn.f32x2 %0, %1, %2, %3;"
        : "=l"(reinterpret_cast<unsigned long long&>(d))
        : "l"(reinterpret_cast<unsigned long long&>(a)),
          "l"(reinterpret_cast<unsigned long long&>(b)),
          "l"(reinterpret_cast<unsigned long long&>(c)));
    return d;
}

__global__ void init_kernel(const float* __restrict__ mu_in) {
    int idx = blockIdx.x * blockDim.x + threadIdx.x;
    if (idx < B_DIM * C_DIM * K_DIM) {
        g_mu[idx] = mu_in[idx & (C_DIM * K_DIM - 1)];
        g_M[idx]  = 0.0f;
    }
    if (idx < B_DIM * K_DIM) g_S[idx] = 0.0f;
}

__global__ __launch_bounds__(512, 2)
void em_stage(const float* __restrict__ x, int last, float* __restrict__ z_out) {
    extern __shared__ float sm[];
    float* sA     = sm;
    float* sB     = sm + SX_SIZE;
    float* s_mu   = sm + MU_OFF;
    float* s_part = sm + PART_OFF;
    float* s_z    = sm + Z_OFF;
    float* s_S    = sm + S_OFF;

    const int tid  = threadIdx.x;
    const int warp = tid >> 5, lane = tid & 31;
    const int b    = blockIdx.y;
    const float* xb = x + (size_t)b * C_DIM * N_DIM;

    // loader / p2 mapping: c = tid>>1, n-half = tid&1
    const int lc = tid >> 1, lh = tid & 1;
    const float* gld = xb + (size_t)lc * N_DIM + lh * 16;
    const int sxoff = lc * SX_STRIDE + lh * 16;

    // reduce mapping: one thread per (virtual n, k)
    const int vn = tid >> 3, vk = tid & 7;

    #pragma unroll
    for (int it = 0; it < 4; ++it) {
        int i = it * 512 + tid;
        s_mu[i] = g_mu[b * (C_DIM * K_DIM) + i];
    }
    if (tid < 8) s_S[tid] = 0.0f;

    float2 M0 = {0.f,0.f}, M1 = {0.f,0.f}, M2 = {0.f,0.f}, M3 = {0.f,0.f};
    float Sacc = 0.0f;

    const int t0 = blockIdx.x;          // 0..31

    // ---- prologue: tile t0 -> sA ; tile t0+GR -> regs ----
    float4 r0, r1, r2, r3;
    {
        const float* g = gld + (size_t)t0 * NB;
        r0 = *(const float4*)(g + 0);  r1 = *(const float4*)(g + 4);
        r2 = *(const float4*)(g + 8);  r3 = *(const float4*)(g + 12);
        float* d = sA + sxoff;
        d[0]=r0.x; d[1]=r0.y; d[2]=r0.z; d[3]=r0.w;
        d[4]=r1.x; d[5]=r1.y; d[6]=r1.z; d[7]=r1.w;
        d[8]=r2.x; d[9]=r2.y; d[10]=r2.z; d[11]=r2.w;
        d[12]=r3.x; d[13]=r3.y; d[14]=r3.z; d[15]=r3.w;
    }
    {
        const float* g = gld + (size_t)(t0 + GR) * NB;
        r0 = *(const float4*)(g + 0);  r1 = *(const float4*)(g + 4);
        r2 = *(const float4*)(g + 8);  r3 = *(const float4*)(g + 12);
    }

    for (int t = t0; t < NT; t += 2 * GR) {
        // ---- stage tile t+GR -> sB ----
        {
            float* d = sB + sxoff;
            d[0]=r0.x; d[1]=r0.y; d[2]=r0.z; d[3]=r0.w;
            d[4]=r1.x; d[5]=r1.y; d[6]=r1.z; d[7]=r1.w;
            d[8]=r2.x; d[9]=r2.y; d[10]=r2.z; d[11]=r2.w;
            d[12]=r3.x; d[13]=r3.y; d[14]=r3.z; d[15]=r3.w;
        }
        __syncthreads();

        // ===== phase 1 over PAIR: c-slice 16/warp, lane = n in each slot =====
        {
            float2 A0={0.f,0.f},A1={0.f,0.f},A2={0.f,0.f},A3={0.f,0.f};
            float2 A4={0.f,0.f},A5={0.f,0.f},A6={0.f,0.f},A7={0.f,0.f};
            const float*  xpA = sA + warp * (16 * SX_STRIDE) + lane;
            const float*  xpB = sB + warp * (16 * SX_STRIDE) + lane;
            const float4* mp  = (const float4*)(s_mu + warp * 128);
            #pragma unroll
            for (int i = 0; i < 16; ++i) {
                float xa = xpA[i * SX_STRIDE];
                float xc = xpB[i * SX_STRIDE];
                float4 m0 = mp[2*i], m1 = mp[2*i+1];     // broadcast, amortized over 2 tiles
                float2 x0 = make_float2(xa, xa);
                float2 x1 = make_float2(xc, xc);
                A0 = ffma2(x0, make_float2(m0.x, m0.y), A0);
                A1 = ffma2(x0, make_float2(m0.z, m0.w), A1);
                A2 = ffma2(x0, make_float2(m1.x, m1.y), A2);
                A3 = ffma2(x0, make_float2(m1.z, m1.w), A3);
                A4 = ffma2(x1, make_float2(m0.x, m0.y), A4);
                A5 = ffma2(x1, make_float2(m0.z, m0.w), A5);
                A6 = ffma2(x1, make_float2(m1.x, m1.y), A6);
                A7 = ffma2(x1, make_float2(m1.z, m1.w), A7);
            }
            int sw = (lane >> 2) & 7;
            float* pb = s_part + warp * 520 + lane * 8;      // vn = lane (slot A)
            pb[0^sw]=A0.x; pb[1^sw]=A0.y; pb[2^sw]=A1.x; pb[3^sw]=A1.y;
            pb[4^sw]=A2.x; pb[5^sw]=A2.y; pb[6^sw]=A3.x; pb[7^sw]=A3.y;
            float* pb2 = pb + 256;                           // vn = lane+32 (slot B)
            pb2[0^sw]=A4.x; pb2[1^sw]=A4.y; pb2[2^sw]=A5.x; pb2[3^sw]=A5.y;
            pb2[4^sw]=A6.x; pb2[5^sw]=A6.y; pb2[6^sw]=A7.x; pb2[7^sw]=A7.y;
        }
        // prefetch tile t+2*GR (overlaps staging visibility barrier)
        {
            int tc = t + 2 * GR;
            const float* g = gld + (size_t)((tc < NT) ? tc : t0) * NB;
            r0 = *(const float4*)(g + 0);  r1 = *(const float4*)(g + 4);
            r2 = *(const float4*)(g + 8);  r3 = *(const float4*)(g + 12);
        }
        __syncthreads();

        // ===== reduce over 16 c-slices + softmax : 1 thread per (vn, k) =====
        {
            int col = vn * 8 + (vk ^ ((vn >> 2) & 7));
            float v = 0.f;
            #pragma unroll
            for (int w = 0; w < 16; ++w)
                v += s_part[w * 520 + col];
            v *= KAPPA;
            float mx = v;
            mx = fmaxf(mx, __shfl_xor_sync(~0u, mx, 1));
            mx = fmaxf(mx, __shfl_xor_sync(~0u, mx, 2));
            mx = fmaxf(mx, __shfl_xor_sync(~0u, mx, 4));
            float e = __expf(v - mx);
            float s = e;
            s += __shfl_xor_sync(~0u, s, 1);
            s += __shfl_xor_sync(~0u, s, 2);
            s += __shfl_xor_sync(~0u, s, 4);
            float z = e / s;
            s_z[vn * 8 + ((vn >> 4) << 2) + vk] = z;
            Sacc += z;
            if (last) {
                int tile = (vn < 32) ? t : (t + GR);
                z_out[(((size_t)b * N_DIM + (size_t)tile * NB + (vn & 31)) << 3) + vk] = z;
            }
        }
        __syncthreads();

        // ===== phase 2: both slots into register M =====
        {
            const float* xrA = sA + sxoff;
            const float* zrA = s_z + lh * 132;
            #pragma unroll
            for (int j = 0; j < 16; ++j) {
                float  xv = xrA[j];
                float2 xs = make_float2(xv, xv);
                float4 za = *(const float4*)(zrA + 8*j);
                float4 zb = *(const float4*)(zrA + 8*j + 4);
                M0 = ffma2(xs, make_float2(za.x, za.y), M0);
                M1 = ffma2(xs, make_float2(za.z, za.w), M1);
                M2 = ffma2(xs, make_float2(zb.x, zb.y), M2);
                M3 = ffma2(xs, make_float2(zb.z, zb.w), M3);
            }
            const float* xrB = sB + sxoff;
            const float* zrB = s_z + 264 + lh * 132;    // vn = 32 + lh*16 + j
            #pragma unroll
            for (int j = 0; j < 16; ++j) {
                float  xv = xrB[j];
                float2 xs = make_float2(xv, xv);
                float4 za = *(const float4*)(zrB + 8*j);
                float4 zb = *(const float4*)(zrB + 8*j + 4);
                M0 = ffma2(xs, make_float2(za.x, za.y), M0);
                M1 = ffma2(xs, make_float2(za.z, za.w), M1);
                M2 = ffma2(xs, make_float2(zb.x, zb.y), M2);
                M3 = ffma2(xs, make_float2(zb.z, zb.w), M3);
            }
        }
        __syncthreads();   // p2 reads done -> sA may be overwritten

        // ---- stage tile t+2GR -> sA ; prefetch t+3GR -> regs ----
        if (t + 2 * GR < NT) {
            float* d = sA + sxoff;
            d[0]=r0.x; d[1]=r0.y; d[2]=r0.z; d[3]=r0.w;
            d[4]=r1.x; d[5]=r1.y; d[6]=r1.z; d[7]=r1.w;
            d[8]=r2.x; d[9]=r2.y; d[10]=r2.z; d[11]=r2.w;
            d[12]=r3.x; d[13]=r3.y; d[14]=r3.z; d[15]=r3.w;
            int td = t + 3 * GR;
            const float* g = gld + (size_t)((td < NT) ? td : t0) * NB;
            r0 = *(const float4*)(g + 0);  r1 = *(const float4*)(g + 4);
            r2 = *(const float4*)(g + 8);  r3 = *(const float4*)(g + 12);
        }
        // no sync needed here: next loop-top writes sB (readers done at post-p2
        // sync) and the sync after that covers sA visibility before p1.
    }

    // ---- epilogue: merge lh pairs, flush M and S ----
    M0.x += __shfl_xor_sync(~0u, M0.x, 1);  M0.y += __shfl_xor_sync(~0u, M0.y, 1);
    M1.x += __shfl_xor_sync(~0u, M1.x, 1);  M1.y += __shfl_xor_sync(~0u, M1.y, 1);
    M2.x += __shfl_xor_sync(~0u, M2.x, 1);  M2.y += __shfl_xor_sync(~0u, M2.y, 1);
    M3.x += __shfl_xor_sync(~0u, M3.x, 1);  M3.y += __shfl_xor_sync(~0u, M3.y, 1);
    if (lh == 0) {
        float* Mp = g_M + ((size_t)b * C_DIM + lc) * K_DIM;
        atomicAdd(Mp + 0, M0.x); atomicAdd(Mp + 1, M0.y);
        atomicAdd(Mp + 2, M1.x); atomicAdd(Mp + 3, M1.y);
        atomicAdd(Mp + 4, M2.x); atomicAdd(Mp + 5, M2.y);
        atomicAdd(Mp + 6, M3.x); atomicAdd(Mp + 7, M3.y);
    }
    Sacc += __shfl_xor_sync(~0u, Sacc, 8);
    Sacc += __shfl_xor_sync(~0u, Sacc, 16);
    if (lane < 8) atomicAdd(s_S + lane, Sacc);
    __syncthreads();
    if (tid < 8) atomicAdd(g_S + b * K_DIM + tid, s_S[tid]);
}

__global__ void finalize_kernel(int last, float* __restrict__ mu_out) {
    const int k = blockIdx.x;
    const int b = blockIdx.y;
    const int c = threadIdx.x;
    __shared__ float red[256];

    float S = g_S[b * K_DIM + k];
    float val = g_M[((size_t)b * C_DIM + c) * K_DIM + k] / (1e-6f + S);

    red[c] = val * val;
    __syncthreads();
    for (int s = 128; s > 0; s >>= 1) {
        if (c < s) red[c] += red[c + s];
        __syncthreads();
    }
    float m = val / (1e-6f + sqrtf(red[0]));

    g_mu[((size_t)b * C_DIM + c) * K_DIM + k] = m;
    g_M [((size_t)b * C_DIM + c) * K_DIM + k] = 0.0f;
    if (c == 0) g_S[b * K_DIM + k] = 0.0f;
    if (last) mu_out[((size_t)b * K_DIM + k) * C_DIM + c] = m;
}

__global__ void zdiv_kernel(float* __restrict__ z) {
    int idx = blockIdx.x * blockDim.x + threadIdx.x;
    if (idx < B_DIM * N_DIM * K_DIM) {
        int k = idx & 7;
        int b = idx >> 17;
        z[idx] = z[idx] / (1e-6f + g_S[b * K_DIM + k]);
    }
}

extern "C" void kernel_launch(void* const* d_in, const int* in_sizes, int n_in,
                              void* d_out, int out_size) {
    const float* x     = (const float*)d_in[0];
    const float* mu_in = (const float*)d_in[1];
    float* out    = (float*)d_out;
    float* mu_out = out;
    float* z_out  = out + B_DIM * K_DIM * C_DIM;

    cudaFuncSetAttribute(em_stage, cudaFuncAttributeMaxDynamicSharedMemorySize, SMEM_BYTES);

    init_kernel<<<128, 256>>>(mu_in);
    for (int s = 0; s < NSTAGES; ++s) {
        int last = (s == NSTAGES - 1);
        em_stage<<<dim3(GR, B_DIM), 512, SMEM_BYTES>>>(x, last, z_out);
        if (last) zdiv_kernel<<<(B_DIM * N_DIM * K_DIM) / 256, 256>>>(z_out);
        finalize_kernel<<<dim3(K_DIM, B_DIM), 256>>>(last, mu_out);
    }
}